// round 15
// baseline (speedup 1.0000x reference)
#include <cuda_runtime.h>
#include <cuda_bf16.h>
#include <cuda_fp16.h>
#include <cstdint>

#define EMBED   1280
#define NHEADS  32
#define HDIM    40
#define BSZV    2
#define TGT     1024
#define PAST    1024
#define SEQ     2048
#define SCALING 0.15811388300841897f

#define KP      2560                  // QKV logical K' = 2*1280 (A split hi|lo)
#define KC      32
#define NCH     (KP / KC)             // 80 (QKV)
#define NCHO    40                    // out-proj: single-pass fp16, K=1280
#define ROWB    80

// ---------------------------------------------------------------------------
// device scratch
// ---------------------------------------------------------------------------
__device__ __align__(256) float g_q[BSZV * NHEADS * TGT * HDIM];
__device__ __align__(256) __half g_Axh[2048 * KP];       // X split   [2048, 2560]
__device__ __align__(256) __half g_Aattnh[2048 * 1280];  // attn out fp16
__device__ __align__(256) __half g_Bqkvh[3840 * 1280];   // Wq|Wk|Wv fp16
__device__ __align__(256) __half g_Boh[1280 * 1280];     // Wo fp16
__device__ __align__(256) __half g_Kh[64 * 2048 * 48];   // K cache fp16 (pad unused)
__device__ __align__(256) __half g_Vt[64 * 48 * 2048];   // V^T fp16 (rows 40..47 unused)

// ---------------------------------------------------------------------------
// mma.sync / ldmatrix / cp.async helpers
// ---------------------------------------------------------------------------
__device__ __forceinline__ void mma16816h(float* d, const uint32_t* a, const uint32_t* b) {
    asm volatile(
        "mma.sync.aligned.m16n8k16.row.col.f32.f16.f16.f32 "
        "{%0,%1,%2,%3}, {%4,%5,%6,%7}, {%8,%9}, {%0,%1,%2,%3};"
        : "+f"(d[0]), "+f"(d[1]), "+f"(d[2]), "+f"(d[3])
        : "r"(a[0]), "r"(a[1]), "r"(a[2]), "r"(a[3]), "r"(b[0]), "r"(b[1]));
}
__device__ __forceinline__ void mma16808h(float* d, const uint32_t* a, uint32_t b0) {
    asm volatile(
        "mma.sync.aligned.m16n8k8.row.col.f32.f16.f16.f32 "
        "{%0,%1,%2,%3}, {%4,%5}, {%6}, {%0,%1,%2,%3};"
        : "+f"(d[0]), "+f"(d[1]), "+f"(d[2]), "+f"(d[3])
        : "r"(a[0]), "r"(a[1]), "r"(b0));
}
__device__ __forceinline__ void ldm4(uint32_t a, uint32_t* r) {
    asm volatile("ldmatrix.sync.aligned.m8n8.x4.shared.b16 {%0,%1,%2,%3}, [%4];"
                 : "=r"(r[0]), "=r"(r[1]), "=r"(r[2]), "=r"(r[3]) : "r"(a));
}
__device__ __forceinline__ uint32_t packh(float x, float y) {
    __half2 h = __halves2half2(__float2half_rn(x), __float2half_rn(y));
    return *reinterpret_cast<uint32_t*>(&h);
}
__device__ __forceinline__ uint32_t smem_u32(const void* p) {
    uint32_t a;
    asm("{ .reg .u64 t; cvta.to.shared.u64 t, %1; cvt.u32.u64 %0, t; }" : "=r"(a) : "l"(p));
    return a;
}
__device__ __forceinline__ void cp16(uint32_t dst, const void* src) {
    asm volatile("cp.async.cg.shared.global [%0], [%1], 16;"
                 :: "r"(dst), "l"(__cvta_generic_to_global(src)) : "memory");
}
__device__ __forceinline__ void cp_commit() {
    asm volatile("cp.async.commit_group;" ::: "memory");
}
template <int N>
__device__ __forceinline__ void cp_wait() {
    asm volatile("cp.async.wait_group %0;" :: "n"(N) : "memory");
}

// ---------------------------------------------------------------------------
// merged prep kernel: dispatch by blockIdx.x
//   [0, 2560)    copy_past (+fp16 caches)
//   [2560, 5120) X fp16x2 split
//   [5120, 11520) W -> fp16 (4 weights)
// ---------------------------------------------------------------------------
#define PREP_COPY  2560
#define PREP_SPLIT 2560
#define PREP_W     6400
#define PREP_TOTAL (PREP_COPY + PREP_SPLIT + PREP_W)

__global__ __launch_bounds__(256) void prep_kernel(
    const float4* __restrict__ pk, const float4* __restrict__ pv,
    float4* __restrict__ ko, float4* __restrict__ vo,
    const float4* __restrict__ X,
    const float* __restrict__ Wq, const float* __restrict__ Wk,
    const float* __restrict__ Wv, const float* __restrict__ Wo)
{
    __shared__ float s[32][33];
    const int blk = blockIdx.x, tid = threadIdx.x;

    if (blk < PREP_COPY) {
        int i = blk * 256 + tid;                      // < 655360
        const int per_bh = PAST * HDIM / 4;           // 10240
        int bh = i / per_bh;
        int r  = i - bh * per_bh;
        float4 kv4 = pk[i], vv4 = pv[i];
        int o  = bh * (SEQ * HDIM / 4) + r;
        ko[o] = kv4;
        vo[o] = vv4;
        int key = r / 10, d0 = (r - key * 10) * 4;
        __half2 k01 = __halves2half2(__float2half_rn(kv4.x), __float2half_rn(kv4.y));
        __half2 k23 = __halves2half2(__float2half_rn(kv4.z), __float2half_rn(kv4.w));
        __half* kh = g_Kh + ((size_t)bh * 2048 + key) * 48 + d0;
        *reinterpret_cast<__half2*>(kh)     = k01;
        *reinterpret_cast<__half2*>(kh + 2) = k23;
        __half* vt = g_Vt + ((size_t)(bh * 48 + d0)) * 2048 + key;
        vt[0]        = __float2half_rn(vv4.x);
        vt[2048]     = __float2half_rn(vv4.y);
        vt[2 * 2048] = __float2half_rn(vv4.z);
        vt[3 * 2048] = __float2half_rn(vv4.w);
    } else if (blk < PREP_COPY + PREP_SPLIT) {
        int i = (blk - PREP_COPY) * 256 + tid;        // < 655360
        int m = i / 320, kq = (i - m * 320) * 4;
        float4 v = X[i];
        __half hx = __float2half_rn(v.x), hy = __float2half_rn(v.y);
        __half hz = __float2half_rn(v.z), hw = __float2half_rn(v.w);
        __half* row = g_Axh + (size_t)m * KP;
        *reinterpret_cast<__half2*>(row + kq)     = __halves2half2(hx, hy);
        *reinterpret_cast<__half2*>(row + kq + 2) = __halves2half2(hz, hw);
        *reinterpret_cast<__half2*>(row + 1280 + kq) =
            __halves2half2(__float2half_rn(v.x - __half2float(hx)),
                           __float2half_rn(v.y - __half2float(hy)));
        *reinterpret_cast<__half2*>(row + 1280 + kq + 2) =
            __halves2half2(__float2half_rn(v.z - __half2float(hz)),
                           __float2half_rn(v.w - __half2float(hw)));
    } else {
        int idx = blk - (PREP_COPY + PREP_SPLIT);     // < 6400
        int sel = idx / 1600;
        int rem = idx - sel * 1600;
        int e0 = (rem % 40) * 32, k0 = (rem / 40) * 32;
        const float* W = (sel == 0) ? Wq : (sel == 1) ? Wk : (sel == 2) ? Wv : Wo;
        __half* dst = (sel < 3) ? (g_Bqkvh + (size_t)sel * 1280 * 1280) : g_Boh;
        int tx = tid & 31, ty = tid >> 5;
        #pragma unroll
        for (int j = 0; j < 4; j++)
            s[ty + j * 8][tx] = W[(k0 + ty + j * 8) * 1280 + e0 + tx];
        __syncthreads();
        int kk = tid & 15, ee = tid >> 4;
        int k2 = kk * 2;
        #pragma unroll
        for (int j = 0; j < 2; j++) {
            int e_loc = ee + j * 16;
            __half2 hv = __halves2half2(__float2half_rn(s[k2][e_loc]),
                                        __float2half_rn(s[k2 + 1][e_loc]));
            *reinterpret_cast<__half2*>(dst + (size_t)(e0 + e_loc) * 1280 + k0 + k2) = hv;
        }
    }
}

__device__ __forceinline__ int bcol_of(int c) {
    return (c < 40 ? c : c - 40) * KC;
}

// ---------------------------------------------------------------------------
// QKV mainloop, 128x128 tile (at HMMA ceiling — unchanged)
// ---------------------------------------------------------------------------
__device__ __forceinline__ void mma_tile(
    const __half* __restrict__ A, const __half* __restrict__ B,
    int m0, int n0, char* smA, char* smB, float acc[2][8][4])
{
    const int tid = threadIdx.x, lane = tid & 31, w = tid >> 5;
    const int wm = w & 3, wn = w >> 2;
    const uint32_t Ab = smem_u32(smA), Bb = smem_u32(smB);

    const uint32_t a_row_off = (uint32_t)(wm * 32 + (lane & 15)) * ROWB + (lane >> 4) * 16;
    const uint32_t b_row_off = (uint32_t)(wn * 64 + (lane & 7) + (lane >> 4) * 8) * ROWB
                             + ((lane >> 3) & 1) * 16;

    auto issue = [&](int c, int buf) {
        const uint32_t ab = Ab + buf * (128 * ROWB), bb = Bb + buf * (128 * ROWB);
        const int bc = bcol_of(c);
        #pragma unroll
        for (int i = 0; i < 2; i++) {
            int idx = tid + i * 256;
            int rr = idx >> 2, uu = idx & 3;
            cp16(ab + rr * ROWB + uu * 16,
                 A + (size_t)(m0 + rr) * KP + c * KC + uu * 8);
            cp16(bb + rr * ROWB + uu * 16,
                 B + (size_t)(n0 + rr) * 1280 + bc + uu * 8);
        }
        cp_commit();
    };

    issue(0, 0);
    for (int c = 0; c < NCH; c++) {
        if (c + 1 < NCH) issue(c + 1, (c + 1) & 1);
        if (c + 1 < NCH) cp_wait<1>(); else cp_wait<0>();
        __syncthreads();
        const uint32_t ab = Ab + (c & 1) * (128 * ROWB);
        const uint32_t bb = Bb + (c & 1) * (128 * ROWB);
        #pragma unroll
        for (int ks = 0; ks < 2; ks++) {
            uint32_t bf[4][4];
            #pragma unroll
            for (int nb = 0; nb < 4; nb++)
                ldm4(bb + nb * (16 * ROWB) + b_row_off + ks * 32, bf[nb]);
            #pragma unroll
            for (int mi = 0; mi < 2; mi++) {
                uint32_t af[4];
                ldm4(ab + mi * (16 * ROWB) + a_row_off + ks * 32, af);
                #pragma unroll
                for (int nb = 0; nb < 4; nb++) {
                    mma16816h(acc[mi][2 * nb],     af, bf[nb]);
                    mma16816h(acc[mi][2 * nb + 1], af, bf[nb] + 2);
                }
            }
        }
        __syncthreads();
    }
}

// ---------------------------------------------------------------------------
// out-proj mainloop: 64x64 tile, fp16 single-pass. 8 warps (wm 2 x wn 4),
// each warp 32(M) x 16(N). grid 640 CTAs -> better latency hiding.
// ---------------------------------------------------------------------------
__device__ __forceinline__ void mma_tile64(
    const __half* __restrict__ A, const __half* __restrict__ B,
    int m0, int n0, char* smA, char* smB, float acc[2][2][4])
{
    const int tid = threadIdx.x, lane = tid & 31, w = tid >> 5;
    const int wm = w & 1, wn = w >> 1;
    const uint32_t Ab = smem_u32(smA), Bb = smem_u32(smB);

    const uint32_t a_row_off = (uint32_t)(wm * 32 + (lane & 15)) * ROWB + (lane >> 4) * 16;
    const uint32_t b_row_off = (uint32_t)(wn * 16 + (lane & 7) + (lane >> 4) * 8) * ROWB
                             + ((lane >> 3) & 1) * 16;

    auto issue = [&](int c, int buf) {
        const uint32_t ab = Ab + buf * (64 * ROWB), bb = Bb + buf * (64 * ROWB);
        int rr = tid >> 2, uu = tid & 3;
        cp16(ab + rr * ROWB + uu * 16, A + (size_t)(m0 + rr) * 1280 + c * KC + uu * 8);
        cp16(bb + rr * ROWB + uu * 16, B + (size_t)(n0 + rr) * 1280 + c * KC + uu * 8);
        cp_commit();
    };

    issue(0, 0);
    for (int c = 0; c < NCHO; c++) {
        if (c + 1 < NCHO) issue(c + 1, (c + 1) & 1);
        if (c + 1 < NCHO) cp_wait<1>(); else cp_wait<0>();
        __syncthreads();
        const uint32_t ab = Ab + (c & 1) * (64 * ROWB);
        const uint32_t bb = Bb + (c & 1) * (64 * ROWB);
        #pragma unroll
        for (int ks = 0; ks < 2; ks++) {
            uint32_t bf[4];
            ldm4(bb + b_row_off + ks * 32, bf);
            #pragma unroll
            for (int mi = 0; mi < 2; mi++) {
                uint32_t af[4];
                ldm4(ab + mi * (16 * ROWB) + a_row_off + ks * 32, af);
                mma16816h(acc[mi][0], af, bf);
                mma16816h(acc[mi][1], af, bf + 2);
            }
        }
        __syncthreads();
    }
}

// ---------------------------------------------------------------------------
// GEMM kernel A: fused QKV projection. grid (16, 30)
// ---------------------------------------------------------------------------
__global__ __launch_bounds__(256)
void gemm_qkv_mma(const float* __restrict__ bq, const float* __restrict__ bk,
                  const float* __restrict__ bv,
                  float* __restrict__ k_out, float* __restrict__ v_out)
{
    __shared__ __align__(16) char smA[2 * 128 * ROWB];
    __shared__ __align__(16) char smB[2 * 128 * ROWB];
    float acc[2][8][4];
    #pragma unroll
    for (int i = 0; i < 2; i++)
        #pragma unroll
        for (int j = 0; j < 8; j++)
            #pragma unroll
            for (int r = 0; r < 4; r++) acc[i][j][r] = 0.f;

    const int m0 = blockIdx.x * 128;
    mma_tile(g_Axh, g_Bqkvh, m0, blockIdx.y * 128, smA, smB, acc);

    const int lane = threadIdx.x & 31, w = threadIdx.x >> 5;
    const int wm = w & 3, wn = w >> 2;
    const int which = blockIdx.y / 10;
    const int ebase = (blockIdx.y % 10) * 128 + wn * 64;

    #pragma unroll
    for (int mi = 0; mi < 2; mi++)
        #pragma unroll
        for (int ni = 0; ni < 8; ni++)
            #pragma unroll
            for (int r = 0; r < 4; r++) {
                int m = m0 + wm * 32 + mi * 16 + (lane >> 2) + ((r >> 1) & 1) * 8;
                int e = ebase + ni * 8 + (lane & 3) * 2 + (r & 1);
                int bb = m >> 10, t = m & 1023;
                int h = e / HDIM, d = e - h * HDIM;
                int bh = bb * NHEADS + h;
                float v = acc[mi][ni][r];
                if (which == 0) {
                    g_q[((size_t)bh * TGT + t) * HDIM + d] = (v + bq[e]) * SCALING;
                } else if (which == 1) {
                    float kv = v + bk[e];
                    k_out[((size_t)bh * SEQ + PAST + t) * HDIM + d] = kv;
                    g_Kh[((size_t)bh * 2048 + PAST + t) * 48 + d] = __float2half_rn(kv);
                } else {
                    float vv = v + bv[e];
                    v_out[((size_t)bh * SEQ + PAST + t) * HDIM + d] = vv;
                    g_Vt[((size_t)(bh * 48 + d)) * 2048 + PAST + t] = __float2half_rn(vv);
                }
            }
}

// ---------------------------------------------------------------------------
// GEMM kernel B: output projection. grid (32, 20), 64x64 tiles
// ---------------------------------------------------------------------------
__global__ __launch_bounds__(256)
void gemm_out_mma(const float* __restrict__ bo, float* __restrict__ out)
{
    __shared__ __align__(16) char smA[2 * 64 * ROWB];
    __shared__ __align__(16) char smB[2 * 64 * ROWB];
    float acc[2][2][4];
    #pragma unroll
    for (int i = 0; i < 2; i++)
        #pragma unroll
        for (int j = 0; j < 2; j++)
            #pragma unroll
            for (int r = 0; r < 4; r++) acc[i][j][r] = 0.f;

    const int m0 = blockIdx.x * 64;
    const int n0 = blockIdx.y * 64;
    mma_tile64(g_Aattnh, g_Boh, m0, n0, smA, smB, acc);

    const int lane = threadIdx.x & 31, w = threadIdx.x >> 5;
    const int wm = w & 1, wn = w >> 1;

    #pragma unroll
    for (int mi = 0; mi < 2; mi++)
        #pragma unroll
        for (int ni = 0; ni < 2; ni++)
            #pragma unroll
            for (int r = 0; r < 4; r++) {
                int m = m0 + wm * 32 + mi * 16 + (lane >> 2) + ((r >> 1) & 1) * 8;
                int e = n0 + wn * 16 + ni * 8 + (lane & 3) * 2 + (r & 1);
                out[(size_t)m * EMBED + e] = acc[mi][ni][r] + bo[e];
            }
}

// ---------------------------------------------------------------------------
// HMMA flash attention. grid (64 bh, 8 qtiles of 128), 256 threads.
// QK: 2x k16 + 1x k8 (real dims only). PV: 5 vt tiles (40 dims, no pad).
// ---------------------------------------------------------------------------
__global__ __launch_bounds__(256) void attn_hmma()
{
    __shared__ __align__(16) __half Kbuf[128 * 56];
    __shared__ __align__(16) __half Vbuf[40 * 136];

    const int bh = blockIdx.x;
    const int qt = blockIdx.y;
    const int b  = bh >> 5, h = bh & 31;
    const int tid = threadIdx.x, lane = tid & 31, w = tid >> 5;
    const int g = lane >> 2, tig = lane & 3;

    uint32_t qhi[2][4], qtail[2];
    {
        const int t0 = qt * 128 + w * 16 + g;
        const float* Q0 = g_q + ((size_t)bh * 1024 + t0) * 40;
        const float* Q1 = Q0 + 8 * 40;
        #pragma unroll
        for (int ks = 0; ks < 2; ks++)
            #pragma unroll
            for (int j = 0; j < 2; j++) {
                int k0 = ks * 16 + j * 8 + tig * 2;
                qhi[ks][j * 2]     = packh(Q0[k0], Q0[k0 + 1]);
                qhi[ks][j * 2 + 1] = packh(Q1[k0], Q1[k0 + 1]);
            }
        int k0 = 32 + tig * 2;
        qtail[0] = packh(Q0[k0], Q0[k0 + 1]);
        qtail[1] = packh(Q1[k0], Q1[k0 + 1]);
    }

    float m_r[2] = { -1e30f, -1e30f };
    float l_r[2] = { 0.f, 0.f };
    float O[5][4];
    #pragma unroll
    for (int vt = 0; vt < 5; vt++)
        #pragma unroll
        for (int r = 0; r < 4; r++) O[vt][r] = 0.f;

    for (int ch = 0; ch < 16; ch++) {
        {
            const uint32_t* Ks = (const uint32_t*)(g_Kh + ((size_t)bh * 2048 + ch * 128) * 48);
            uint32_t* Kd = (uint32_t*)Kbuf;
            #pragma unroll
            for (int i = 0; i < 12; i++) {
                int idx = tid + i * 256;
                int r = idx / 24, cw = idx - r * 24;
                Kd[r * 28 + cw] = Ks[r * 24 + cw];
            }
            #pragma unroll
            for (int i = 0; i < 10; i++) {
                int idx = tid + i * 256;
                int d = idx >> 6, kw = idx & 63;
                ((uint32_t*)Vbuf)[d * 68 + kw] =
                    ((const uint32_t*)(g_Vt + ((size_t)(bh * 48 + d)) * 2048 + ch * 128))[kw];
            }
        }
        __syncthreads();

        float S[16][4];
        #pragma unroll
        for (int nt = 0; nt < 16; nt++)
            #pragma unroll
            for (int r = 0; r < 4; r++) S[nt][r] = 0.f;

        #pragma unroll
        for (int nt = 0; nt < 16; nt++) {
            const __half* brow = Kbuf + (nt * 8 + g) * 56;
            #pragma unroll
            for (int ks = 0; ks < 2; ks++) {
                uint32_t bfr[2];
                const __half* bp = brow + ks * 16 + tig * 2;
                bfr[0] = *(const uint32_t*)bp;
                bfr[1] = *(const uint32_t*)(bp + 8);
                mma16816h(S[nt], qhi[ks], bfr);
            }
            mma16808h(S[nt], qtail, *(const uint32_t*)(brow + 32 + tig * 2));
        }

        #pragma unroll
        for (int rh = 0; rh < 2; rh++) {
            float mx = -1e30f;
            #pragma unroll
            for (int nt = 0; nt < 16; nt++)
                mx = fmaxf(mx, fmaxf(S[nt][rh * 2], S[nt][rh * 2 + 1]));
            mx = fmaxf(mx, __shfl_xor_sync(0xffffffffu, mx, 1));
            mx = fmaxf(mx, __shfl_xor_sync(0xffffffffu, mx, 2));
            float mn   = fmaxf(m_r[rh], mx);
            float corr = __expf(m_r[rh] - mn);
            m_r[rh] = mn;
            float ls = 0.f;
            #pragma unroll
            for (int nt = 0; nt < 16; nt++) {
                float p0 = __expf(S[nt][rh * 2] - mn);
                float p1 = __expf(S[nt][rh * 2 + 1] - mn);
                S[nt][rh * 2] = p0; S[nt][rh * 2 + 1] = p1;
                ls += p0 + p1;
            }
            ls += __shfl_xor_sync(0xffffffffu, ls, 1);
            ls += __shfl_xor_sync(0xffffffffu, ls, 2);
            l_r[rh] = l_r[rh] * corr + ls;
            #pragma unroll
            for (int vt = 0; vt < 5; vt++) {
                O[vt][rh * 2] *= corr; O[vt][rh * 2 + 1] *= corr;
            }
        }

        #pragma unroll
        for (int kk = 0; kk < 8; kk++) {
            uint32_t ap[4];
            #pragma unroll
            for (int p = 0; p < 2; p++) {
                const float* Sp = S[2 * kk + p];
                ap[p * 2]     = packh(Sp[0], Sp[1]);
                ap[p * 2 + 1] = packh(Sp[2], Sp[3]);
            }
            #pragma unroll
            for (int vt = 0; vt < 5; vt++) {
                uint32_t bfr[2];
                const __half* bp = Vbuf + (vt * 8 + g) * 136 + kk * 16 + tig * 2;
                bfr[0] = *(const uint32_t*)bp;
                bfr[1] = *(const uint32_t*)(bp + 8);
                mma16816h(O[vt], ap, bfr);
            }
        }
        __syncthreads();
    }

    // epilogue: plain fp16 write into g_Aattnh (dims 0..39, no guards needed)
    #pragma unroll
    for (int rh = 0; rh < 2; rh++) {
        int t = qt * 128 + w * 16 + g + rh * 8;
        int m = b * 1024 + t;
        float inv = 1.f / l_r[rh];
        __half* row = g_Aattnh + (size_t)m * 1280 + h * 40;
        #pragma unroll
        for (int vt = 0; vt < 5; vt++) {
            int d0 = vt * 8 + tig * 2;
            row[d0]     = __float2half_rn(O[vt][rh * 2]     * inv);
            row[d0 + 1] = __float2half_rn(O[vt][rh * 2 + 1] * inv);
        }
    }
}

// ---------------------------------------------------------------------------
extern "C" void kernel_launch(void* const* d_in, const int* in_sizes, int n_in,
                              void* d_out, int out_size) {
    const float* X  = (const float*)d_in[0];
    const float* pk = (const float*)d_in[1];
    const float* pv = (const float*)d_in[2];
    const float* Wq = (const float*)d_in[3];
    const float* bq = (const float*)d_in[4];
    const float* Wk = (const float*)d_in[5];
    const float* bk = (const float*)d_in[6];
    const float* Wv = (const float*)d_in[7];
    const float* bv = (const float*)d_in[8];
    const float* Wo = (const float*)d_in[9];
    const float* bo = (const float*)d_in[10];

    float* out      = (float*)d_out;
    float* attn_out = out;
    float* k_out    = out + (size_t)BSZV * TGT * EMBED;
    float* v_out    = k_out + (size_t)BSZV * NHEADS * SEQ * HDIM;

    // 1) merged prep: past KV copy + X split + W conversions
    prep_kernel<<<PREP_TOTAL, 256>>>(
        (const float4*)pk, (const float4*)pv, (float4*)k_out, (float4*)v_out,
        (const float4*)X, Wq, Wk, Wv, Wo);
    // 2) fused QKV projection (HMMA fp16, hi|lo split)
    gemm_qkv_mma<<<dim3(16, 30), 256>>>(bq, bk, bv, k_out, v_out);
    // 3) attention (HMMA flash, pad-free MMA set)
    attn_hmma<<<dim3(64, 8), 256>>>();
    // 4) output projection (HMMA fp16, 64x64 tiles, 640 CTAs)
    gemm_out_mma<<<dim3(32, 20), 256>>>(bo, attn_out);
}

// round 16
// speedup vs baseline: 1.0633x; 1.0633x over previous
#include <cuda_runtime.h>
#include <cuda_bf16.h>
#include <cuda_fp16.h>
#include <cstdint>

#define EMBED   1280
#define NHEADS  32
#define HDIM    40
#define BSZV    2
#define TGT     1024
#define PAST    1024
#define SEQ     2048
#define SCALING 0.15811388300841897f

#define KP      2560                  // QKV logical K' = 2*1280 (A split hi|lo)
#define KC      32
#define NCH     (KP / KC)             // 80 (QKV)
#define ROWB    80

#define KCO     64                    // out-proj chunk (fewer barriers)
#define NCHO    (1280 / KCO)          // 20
#define ROWBO   144                   // 128B data + 16B pad

// ---------------------------------------------------------------------------
// device scratch
// ---------------------------------------------------------------------------
__device__ __align__(256) float g_q[BSZV * NHEADS * TGT * HDIM];
__device__ __align__(256) __half g_Axh[2048 * KP];       // X split   [2048, 2560]
__device__ __align__(256) __half g_Aattnh[2048 * 1280];  // attn out fp16 (no split)
__device__ __align__(256) __half g_Bqkvh[3840 * 1280];   // Wq|Wk|Wv fp16
__device__ __align__(256) __half g_Boh[1280 * 1280];     // Wo fp16
__device__ __align__(256) __half g_Kh[64 * 2048 * 48];   // K cache fp16, [bh][key][48]
__device__ __align__(256) __half g_Vt[64 * 48 * 2048];   // V^T fp16,    [bh][dim48][key]

// ---------------------------------------------------------------------------
// mma.sync / ldmatrix / cp.async helpers
// ---------------------------------------------------------------------------
__device__ __forceinline__ void mma16816h(float* d, const uint32_t* a, const uint32_t* b) {
    asm volatile(
        "mma.sync.aligned.m16n8k16.row.col.f32.f16.f16.f32 "
        "{%0,%1,%2,%3}, {%4,%5,%6,%7}, {%8,%9}, {%0,%1,%2,%3};"
        : "+f"(d[0]), "+f"(d[1]), "+f"(d[2]), "+f"(d[3])
        : "r"(a[0]), "r"(a[1]), "r"(a[2]), "r"(a[3]), "r"(b[0]), "r"(b[1]));
}
__device__ __forceinline__ void ldm4(uint32_t a, uint32_t* r) {
    asm volatile("ldmatrix.sync.aligned.m8n8.x4.shared.b16 {%0,%1,%2,%3}, [%4];"
                 : "=r"(r[0]), "=r"(r[1]), "=r"(r[2]), "=r"(r[3]) : "r"(a));
}
__device__ __forceinline__ uint32_t packh(float x, float y) {
    __half2 h = __halves2half2(__float2half_rn(x), __float2half_rn(y));
    return *reinterpret_cast<uint32_t*>(&h);
}
__device__ __forceinline__ uint32_t smem_u32(const void* p) {
    uint32_t a;
    asm("{ .reg .u64 t; cvta.to.shared.u64 t, %1; cvt.u32.u64 %0, t; }" : "=r"(a) : "l"(p));
    return a;
}
__device__ __forceinline__ void cp16(uint32_t dst, const void* src) {
    asm volatile("cp.async.cg.shared.global [%0], [%1], 16;"
                 :: "r"(dst), "l"(__cvta_generic_to_global(src)) : "memory");
}
__device__ __forceinline__ void cp_commit() {
    asm volatile("cp.async.commit_group;" ::: "memory");
}
template <int N>
__device__ __forceinline__ void cp_wait() {
    asm volatile("cp.async.wait_group %0;" :: "n"(N) : "memory");
}

// ---------------------------------------------------------------------------
// merged prep kernel: dispatch by blockIdx.x
//   [0, 2560)          copy_past (+fp16 caches)
//   [2560, 3072)       K-cache pad zeroing (uint4)
//   [3072, 5632)       X fp16x2 split
//   [5632, 12032)      W -> fp16 (4 weights)
// ---------------------------------------------------------------------------
#define PREP_COPY  2560
#define PREP_PAD   512
#define PREP_SPLIT 2560
#define PREP_W     6400
#define PREP_TOTAL (PREP_COPY + PREP_PAD + PREP_SPLIT + PREP_W)

__global__ __launch_bounds__(256) void prep_kernel(
    const float4* __restrict__ pk, const float4* __restrict__ pv,
    float4* __restrict__ ko, float4* __restrict__ vo,
    const float4* __restrict__ X,
    const float* __restrict__ Wq, const float* __restrict__ Wk,
    const float* __restrict__ Wv, const float* __restrict__ Wo)
{
    __shared__ float s[32][33];
    const int blk = blockIdx.x, tid = threadIdx.x;

    if (blk < PREP_COPY) {
        int i = blk * 256 + tid;                      // < 655360
        const int per_bh = PAST * HDIM / 4;           // 10240
        int bh = i / per_bh;
        int r  = i - bh * per_bh;
        float4 kv4 = pk[i], vv4 = pv[i];
        int o  = bh * (SEQ * HDIM / 4) + r;
        ko[o] = kv4;
        vo[o] = vv4;
        int key = r / 10, d0 = (r - key * 10) * 4;
        __half2 k01 = __halves2half2(__float2half_rn(kv4.x), __float2half_rn(kv4.y));
        __half2 k23 = __halves2half2(__float2half_rn(kv4.z), __float2half_rn(kv4.w));
        __half* kh = g_Kh + ((size_t)bh * 2048 + key) * 48 + d0;
        *reinterpret_cast<__half2*>(kh)     = k01;
        *reinterpret_cast<__half2*>(kh + 2) = k23;
        __half* vt = g_Vt + ((size_t)(bh * 48 + d0)) * 2048 + key;
        vt[0]        = __float2half_rn(vv4.x);
        vt[2048]     = __float2half_rn(vv4.y);
        vt[2 * 2048] = __float2half_rn(vv4.z);
        vt[3 * 2048] = __float2half_rn(vv4.w);
    } else if (blk < PREP_COPY + PREP_PAD) {
        int i = (blk - PREP_COPY) * 256 + tid;        // < 131072
        uint4 z = {0u, 0u, 0u, 0u};
        *reinterpret_cast<uint4*>(g_Kh + (size_t)i * 48 + 40) = z;
    } else if (blk < PREP_COPY + PREP_PAD + PREP_SPLIT) {
        int i = (blk - PREP_COPY - PREP_PAD) * 256 + tid;   // < 655360
        int m = i / 320, kq = (i - m * 320) * 4;
        float4 v = X[i];
        __half hx = __float2half_rn(v.x), hy = __float2half_rn(v.y);
        __half hz = __float2half_rn(v.z), hw = __float2half_rn(v.w);
        __half* row = g_Axh + (size_t)m * KP;
        *reinterpret_cast<__half2*>(row + kq)     = __halves2half2(hx, hy);
        *reinterpret_cast<__half2*>(row + kq + 2) = __halves2half2(hz, hw);
        *reinterpret_cast<__half2*>(row + 1280 + kq) =
            __halves2half2(__float2half_rn(v.x - __half2float(hx)),
                           __float2half_rn(v.y - __half2float(hy)));
        *reinterpret_cast<__half2*>(row + 1280 + kq + 2) =
            __halves2half2(__float2half_rn(v.z - __half2float(hz)),
                           __float2half_rn(v.w - __half2float(hw)));
    } else {
        int idx = blk - (PREP_COPY + PREP_PAD + PREP_SPLIT);  // < 6400
        int sel = idx / 1600;
        int rem = idx - sel * 1600;
        int e0 = (rem % 40) * 32, k0 = (rem / 40) * 32;
        const float* W = (sel == 0) ? Wq : (sel == 1) ? Wk : (sel == 2) ? Wv : Wo;
        __half* dst = (sel < 3) ? (g_Bqkvh + (size_t)sel * 1280 * 1280) : g_Boh;
        int tx = tid & 31, ty = tid >> 5;
        #pragma unroll
        for (int j = 0; j < 4; j++)
            s[ty + j * 8][tx] = W[(k0 + ty + j * 8) * 1280 + e0 + tx];
        __syncthreads();
        int kk = tid & 15, ee = tid >> 4;
        int k2 = kk * 2;
        #pragma unroll
        for (int j = 0; j < 2; j++) {
            int e_loc = ee + j * 16;
            __half2 hv = __halves2half2(__float2half_rn(s[k2][e_loc]),
                                        __float2half_rn(s[k2 + 1][e_loc]));
            *reinterpret_cast<__half2*>(dst + (size_t)(e0 + e_loc) * 1280 + k0 + k2) = hv;
        }
    }
}

__device__ __forceinline__ int bcol_of(int c) {
    return (c < 40 ? c : c - 40) * KC;
}

// ---------------------------------------------------------------------------
// QKV mainloop, 128x128 tile (at HMMA ceiling — unchanged)
// ---------------------------------------------------------------------------
__device__ __forceinline__ void mma_tile(
    const __half* __restrict__ A, const __half* __restrict__ B,
    int m0, int n0, char* smA, char* smB, float acc[2][8][4])
{
    const int tid = threadIdx.x, lane = tid & 31, w = tid >> 5;
    const int wm = w & 3, wn = w >> 2;
    const uint32_t Ab = smem_u32(smA), Bb = smem_u32(smB);

    const uint32_t a_row_off = (uint32_t)(wm * 32 + (lane & 15)) * ROWB + (lane >> 4) * 16;
    const uint32_t b_row_off = (uint32_t)(wn * 64 + (lane & 7) + (lane >> 4) * 8) * ROWB
                             + ((lane >> 3) & 1) * 16;

    auto issue = [&](int c, int buf) {
        const uint32_t ab = Ab + buf * (128 * ROWB), bb = Bb + buf * (128 * ROWB);
        const int bc = bcol_of(c);
        #pragma unroll
        for (int i = 0; i < 2; i++) {
            int idx = tid + i * 256;
            int rr = idx >> 2, uu = idx & 3;
            cp16(ab + rr * ROWB + uu * 16,
                 A + (size_t)(m0 + rr) * KP + c * KC + uu * 8);
            cp16(bb + rr * ROWB + uu * 16,
                 B + (size_t)(n0 + rr) * 1280 + bc + uu * 8);
        }
        cp_commit();
    };

    issue(0, 0);
    for (int c = 0; c < NCH; c++) {
        if (c + 1 < NCH) issue(c + 1, (c + 1) & 1);
        if (c + 1 < NCH) cp_wait<1>(); else cp_wait<0>();
        __syncthreads();
        const uint32_t ab = Ab + (c & 1) * (128 * ROWB);
        const uint32_t bb = Bb + (c & 1) * (128 * ROWB);
        #pragma unroll
        for (int ks = 0; ks < 2; ks++) {
            uint32_t bf[4][4];
            #pragma unroll
            for (int nb = 0; nb < 4; nb++)
                ldm4(bb + nb * (16 * ROWB) + b_row_off + ks * 32, bf[nb]);
            #pragma unroll
            for (int mi = 0; mi < 2; mi++) {
                uint32_t af[4];
                ldm4(ab + mi * (16 * ROWB) + a_row_off + ks * 32, af);
                #pragma unroll
                for (int nb = 0; nb < 4; nb++) {
                    mma16816h(acc[mi][2 * nb],     af, bf[nb]);
                    mma16816h(acc[mi][2 * nb + 1], af, bf[nb] + 2);
                }
            }
        }
        __syncthreads();
    }
}

// ---------------------------------------------------------------------------
// out-proj mainloop: 64x64 tile, KCO=64 chunks (20 iters, 16 MMA/warp/chunk)
// 8 warps (wm 2 x wn 4), each warp 32(M) x 16(N).
// ---------------------------------------------------------------------------
__device__ __forceinline__ void mma_tile64(
    const __half* __restrict__ A, const __half* __restrict__ B,
    int m0, int n0, char* smA, char* smB, float acc[2][2][4])
{
    const int tid = threadIdx.x, lane = tid & 31, w = tid >> 5;
    const int wm = w & 1, wn = w >> 1;
    const uint32_t Ab = smem_u32(smA), Bb = smem_u32(smB);

    const uint32_t a_row_off = (uint32_t)(wm * 32 + (lane & 15)) * ROWBO + (lane >> 4) * 16;
    const uint32_t b_row_off = (uint32_t)(wn * 16 + (lane & 7) + (lane >> 4) * 8) * ROWBO
                             + ((lane >> 3) & 1) * 16;

    auto issue = [&](int c, int buf) {
        const uint32_t ab = Ab + buf * (64 * ROWBO), bb = Bb + buf * (64 * ROWBO);
        #pragma unroll
        for (int i = 0; i < 2; i++) {
            int idx = tid + i * 256;              // 0..511
            int rr = idx >> 3, uu = idx & 7;
            cp16(ab + rr * ROWBO + uu * 16,
                 A + (size_t)(m0 + rr) * 1280 + c * KCO + uu * 8);
            cp16(bb + rr * ROWBO + uu * 16,
                 B + (size_t)(n0 + rr) * 1280 + c * KCO + uu * 8);
        }
        cp_commit();
    };

    issue(0, 0);
    for (int c = 0; c < NCHO; c++) {
        if (c + 1 < NCHO) issue(c + 1, (c + 1) & 1);
        if (c + 1 < NCHO) cp_wait<1>(); else cp_wait<0>();
        __syncthreads();
        const uint32_t ab = Ab + (c & 1) * (64 * ROWBO);
        const uint32_t bb = Bb + (c & 1) * (64 * ROWBO);
        #pragma unroll
        for (int ks = 0; ks < 4; ks++) {
            uint32_t bf[4];
            ldm4(bb + b_row_off + ks * 32, bf);
            #pragma unroll
            for (int mi = 0; mi < 2; mi++) {
                uint32_t af[4];
                ldm4(ab + mi * (16 * ROWBO) + a_row_off + ks * 32, af);
                mma16816h(acc[mi][0], af, bf);
                mma16816h(acc[mi][1], af, bf + 2);
            }
        }
        __syncthreads();
    }
}

// ---------------------------------------------------------------------------
// GEMM kernel A: fused QKV projection. grid (16, 30)
// ---------------------------------------------------------------------------
__global__ __launch_bounds__(256)
void gemm_qkv_mma(const float* __restrict__ bq, const float* __restrict__ bk,
                  const float* __restrict__ bv,
                  float* __restrict__ k_out, float* __restrict__ v_out)
{
    __shared__ __align__(16) char smA[2 * 128 * ROWB];
    __shared__ __align__(16) char smB[2 * 128 * ROWB];
    float acc[2][8][4];
    #pragma unroll
    for (int i = 0; i < 2; i++)
        #pragma unroll
        for (int j = 0; j < 8; j++)
            #pragma unroll
            for (int r = 0; r < 4; r++) acc[i][j][r] = 0.f;

    const int m0 = blockIdx.x * 128;
    mma_tile(g_Axh, g_Bqkvh, m0, blockIdx.y * 128, smA, smB, acc);

    const int lane = threadIdx.x & 31, w = threadIdx.x >> 5;
    const int wm = w & 3, wn = w >> 2;
    const int which = blockIdx.y / 10;
    const int ebase = (blockIdx.y % 10) * 128 + wn * 64;

    #pragma unroll
    for (int mi = 0; mi < 2; mi++)
        #pragma unroll
        for (int ni = 0; ni < 8; ni++)
            #pragma unroll
            for (int r = 0; r < 4; r++) {
                int m = m0 + wm * 32 + mi * 16 + (lane >> 2) + ((r >> 1) & 1) * 8;
                int e = ebase + ni * 8 + (lane & 3) * 2 + (r & 1);
                int bb = m >> 10, t = m & 1023;
                int h = e / HDIM, d = e - h * HDIM;
                int bh = bb * NHEADS + h;
                float v = acc[mi][ni][r];
                if (which == 0) {
                    g_q[((size_t)bh * TGT + t) * HDIM + d] = (v + bq[e]) * SCALING;
                } else if (which == 1) {
                    float kv = v + bk[e];
                    k_out[((size_t)bh * SEQ + PAST + t) * HDIM + d] = kv;
                    g_Kh[((size_t)bh * 2048 + PAST + t) * 48 + d] = __float2half_rn(kv);
                } else {
                    float vv = v + bv[e];
                    v_out[((size_t)bh * SEQ + PAST + t) * HDIM + d] = vv;
                    g_Vt[((size_t)(bh * 48 + d)) * 2048 + PAST + t] = __float2half_rn(vv);
                }
            }
}

// ---------------------------------------------------------------------------
// GEMM kernel B: output projection. grid (32, 20), 64x64 tiles, KCO=64
// ---------------------------------------------------------------------------
__global__ __launch_bounds__(256)
void gemm_out_mma(const float* __restrict__ bo, float* __restrict__ out)
{
    __shared__ __align__(16) char smA[2 * 64 * ROWBO];
    __shared__ __align__(16) char smB[2 * 64 * ROWBO];
    float acc[2][2][4];
    #pragma unroll
    for (int i = 0; i < 2; i++)
        #pragma unroll
        for (int j = 0; j < 2; j++)
            #pragma unroll
            for (int r = 0; r < 4; r++) acc[i][j][r] = 0.f;

    const int m0 = blockIdx.x * 64;
    const int n0 = blockIdx.y * 64;
    mma_tile64(g_Aattnh, g_Boh, m0, n0, smA, smB, acc);

    const int lane = threadIdx.x & 31, w = threadIdx.x >> 5;
    const int wm = w & 1, wn = w >> 1;

    #pragma unroll
    for (int mi = 0; mi < 2; mi++)
        #pragma unroll
        for (int ni = 0; ni < 2; ni++)
            #pragma unroll
            for (int r = 0; r < 4; r++) {
                int m = m0 + wm * 32 + mi * 16 + (lane >> 2) + ((r >> 1) & 1) * 8;
                int e = n0 + wn * 16 + ni * 8 + (lane & 3) * 2 + (r & 1);
                out[(size_t)m * EMBED + e] = acc[mi][ni][r] + bo[e];
            }
}

// ---------------------------------------------------------------------------
// HMMA flash attention (exact R14 version). grid (64, 8), 256 threads.
// ---------------------------------------------------------------------------
__global__ __launch_bounds__(256) void attn_hmma()
{
    __shared__ __align__(16) __half Kbuf[128 * 56];
    __shared__ __align__(16) __half Vbuf[48 * 136];

    const int bh = blockIdx.x;
    const int qt = blockIdx.y;
    const int b  = bh >> 5, h = bh & 31;
    const int tid = threadIdx.x, lane = tid & 31, w = tid >> 5;
    const int g = lane >> 2, tig = lane & 3;

    uint32_t qhi[3][4];
    {
        const int t0 = qt * 128 + w * 16 + g;
        const float* Q0 = g_q + ((size_t)bh * 1024 + t0) * 40;
        const float* Q1 = Q0 + 8 * 40;
        #pragma unroll
        for (int ks = 0; ks < 3; ks++)
            #pragma unroll
            for (int j = 0; j < 2; j++) {
                int k0 = ks * 16 + j * 8 + tig * 2;
                float xa0 = (k0     < 40) ? Q0[k0]     : 0.f;
                float xa1 = (k0 + 1 < 40) ? Q0[k0 + 1] : 0.f;
                float xb0 = (k0     < 40) ? Q1[k0]     : 0.f;
                float xb1 = (k0 + 1 < 40) ? Q1[k0 + 1] : 0.f;
                qhi[ks][j * 2]     = packh(xa0, xa1);
                qhi[ks][j * 2 + 1] = packh(xb0, xb1);
            }
    }

    float m_r[2] = { -1e30f, -1e30f };
    float l_r[2] = { 0.f, 0.f };
    float O[6][4];
    #pragma unroll
    for (int vt = 0; vt < 6; vt++)
        #pragma unroll
        for (int r = 0; r < 4; r++) O[vt][r] = 0.f;

    for (int ch = 0; ch < 16; ch++) {
        {
            const uint32_t* Ks = (const uint32_t*)(g_Kh + ((size_t)bh * 2048 + ch * 128) * 48);
            uint32_t* Kd = (uint32_t*)Kbuf;
            #pragma unroll
            for (int i = 0; i < 12; i++) {
                int idx = tid + i * 256;
                int r = idx / 24, cw = idx - r * 24;
                Kd[r * 28 + cw] = Ks[r * 24 + cw];
            }
            #pragma unroll
            for (int i = 0; i < 12; i++) {
                int idx = tid + i * 256;
                int d = idx >> 6, kw = idx & 63;
                ((uint32_t*)Vbuf)[d * 68 + kw] =
                    ((const uint32_t*)(g_Vt + ((size_t)(bh * 48 + d)) * 2048 + ch * 128))[kw];
            }
        }
        __syncthreads();

        float S[16][4];
        #pragma unroll
        for (int nt = 0; nt < 16; nt++)
            #pragma unroll
            for (int r = 0; r < 4; r++) S[nt][r] = 0.f;

        #pragma unroll
        for (int ks = 0; ks < 3; ks++)
            #pragma unroll
            for (int nt = 0; nt < 16; nt++) {
                uint32_t bfr[2];
                const __half* bp = Kbuf + (nt * 8 + g) * 56 + ks * 16 + tig * 2;
                bfr[0] = *(const uint32_t*)bp;
                bfr[1] = *(const uint32_t*)(bp + 8);
                mma16816h(S[nt], qhi[ks], bfr);
            }

        #pragma unroll
        for (int rh = 0; rh < 2; rh++) {
            float mx = -1e30f;
            #pragma unroll
            for (int nt = 0; nt < 16; nt++)
                mx = fmaxf(mx, fmaxf(S[nt][rh * 2], S[nt][rh * 2 + 1]));
            mx = fmaxf(mx, __shfl_xor_sync(0xffffffffu, mx, 1));
            mx = fmaxf(mx, __shfl_xor_sync(0xffffffffu, mx, 2));
            float mn   = fmaxf(m_r[rh], mx);
            float corr = __expf(m_r[rh] - mn);
            m_r[rh] = mn;
            float ls = 0.f;
            #pragma unroll
            for (int nt = 0; nt < 16; nt++) {
                float p0 = __expf(S[nt][rh * 2] - mn);
                float p1 = __expf(S[nt][rh * 2 + 1] - mn);
                S[nt][rh * 2] = p0; S[nt][rh * 2 + 1] = p1;
                ls += p0 + p1;
            }
            ls += __shfl_xor_sync(0xffffffffu, ls, 1);
            ls += __shfl_xor_sync(0xffffffffu, ls, 2);
            l_r[rh] = l_r[rh] * corr + ls;
            #pragma unroll
            for (int vt = 0; vt < 6; vt++) {
                O[vt][rh * 2] *= corr; O[vt][rh * 2 + 1] *= corr;
            }
        }

        #pragma unroll
        for (int kk = 0; kk < 8; kk++) {
            uint32_t ap[4];
            #pragma unroll
            for (int p = 0; p < 2; p++) {
                const float* Sp = S[2 * kk + p];
                ap[p * 2]     = packh(Sp[0], Sp[1]);
                ap[p * 2 + 1] = packh(Sp[2], Sp[3]);
            }
            #pragma unroll
            for (int vt = 0; vt < 6; vt++) {
                uint32_t bfr[2];
                const __half* bp = Vbuf + (vt * 8 + g) * 136 + kk * 16 + tig * 2;
                bfr[0] = *(const uint32_t*)bp;
                bfr[1] = *(const uint32_t*)(bp + 8);
                mma16816h(O[vt], ap, bfr);
            }
        }
        __syncthreads();
    }

    // epilogue: plain fp16 write into g_Aattnh
    #pragma unroll
    for (int rh = 0; rh < 2; rh++) {
        int t = qt * 128 + w * 16 + g + rh * 8;
        int m = b * 1024 + t;
        float inv = 1.f / l_r[rh];
        __half* row = g_Aattnh + (size_t)m * 1280 + h * 40;
        #pragma unroll
        for (int vt = 0; vt < 6; vt++) {
            int d0 = vt * 8 + tig * 2;
            if (d0 < 40)     row[d0]     = __float2half_rn(O[vt][rh * 2]     * inv);
            if (d0 + 1 < 40) row[d0 + 1] = __float2half_rn(O[vt][rh * 2 + 1] * inv);
        }
    }
}

// ---------------------------------------------------------------------------
extern "C" void kernel_launch(void* const* d_in, const int* in_sizes, int n_in,
                              void* d_out, int out_size) {
    const float* X  = (const float*)d_in[0];
    const float* pk = (const float*)d_in[1];
    const float* pv = (const float*)d_in[2];
    const float* Wq = (const float*)d_in[3];
    const float* bq = (const float*)d_in[4];
    const float* Wk = (const float*)d_in[5];
    const float* bk = (const float*)d_in[6];
    const float* Wv = (const float*)d_in[7];
    const float* bv = (const float*)d_in[8];
    const float* Wo = (const float*)d_in[9];
    const float* bo = (const float*)d_in[10];

    float* out      = (float*)d_out;
    float* attn_out = out;
    float* k_out    = out + (size_t)BSZV * TGT * EMBED;
    float* v_out    = k_out + (size_t)BSZV * NHEADS * SEQ * HDIM;

    // 1) merged prep
    prep_kernel<<<PREP_TOTAL, 256>>>(
        (const float4*)pk, (const float4*)pv, (float4*)k_out, (float4*)v_out,
        (const float4*)X, Wq, Wk, Wv, Wo);
    // 2) fused QKV projection (HMMA fp16, hi|lo split)
    gemm_qkv_mma<<<dim3(16, 30), 256>>>(bq, bk, bv, k_out, v_out);
    // 3) attention (HMMA flash, R14 version)
    attn_hmma<<<dim3(64, 8), 256>>>();
    // 4) output projection (HMMA fp16, 64x64 tiles, KCO=64)
    gemm_out_mma<<<dim3(32, 20), 256>>>(bo, attn_out);
}

// round 17
// speedup vs baseline: 1.2868x; 1.2101x over previous
#include <cuda_runtime.h>
#include <cuda_bf16.h>
#include <cuda_fp16.h>
#include <cstdint>

#define EMBED   1280
#define NHEADS  32
#define HDIM    40
#define BSZV    2
#define TGT     1024
#define PAST    1024
#define SEQ     2048
#define SCALING 0.15811388300841897f

#define KP      2560                  // QKV A storage: [hi | lo]
#define KC      32
#define NCH     (KP / KC)             // 80 (full hi+lo, Q only)
#define NCH_HI  40                    // hi-only (K, V)
#define ROWB    80

#define KCO     64                    // out-proj chunk
#define NCHO    (1280 / KCO)          // 20
#define ROWBO   144

// ---------------------------------------------------------------------------
// device scratch
// ---------------------------------------------------------------------------
__device__ __align__(256) float g_q[BSZV * NHEADS * TGT * HDIM];
__device__ __align__(256) __half g_Axh[2048 * KP];       // X split   [2048, 2560]
__device__ __align__(256) __half g_Aattnh[2048 * 1280];  // attn out fp16
__device__ __align__(256) __half g_Bqkvh[3840 * 1280];   // Wq|Wk|Wv fp16
__device__ __align__(256) __half g_Boh[1280 * 1280];     // Wo fp16
__device__ __align__(256) __half g_Kh[64 * 2048 * 48];   // K cache fp16
__device__ __align__(256) __half g_Vt[64 * 48 * 2048];   // V^T fp16

// ---------------------------------------------------------------------------
// mma.sync / ldmatrix / cp.async helpers
// ---------------------------------------------------------------------------
__device__ __forceinline__ void mma16816h(float* d, const uint32_t* a, const uint32_t* b) {
    asm volatile(
        "mma.sync.aligned.m16n8k16.row.col.f32.f16.f16.f32 "
        "{%0,%1,%2,%3}, {%4,%5,%6,%7}, {%8,%9}, {%0,%1,%2,%3};"
        : "+f"(d[0]), "+f"(d[1]), "+f"(d[2]), "+f"(d[3])
        : "r"(a[0]), "r"(a[1]), "r"(a[2]), "r"(a[3]), "r"(b[0]), "r"(b[1]));
}
__device__ __forceinline__ void ldm4(uint32_t a, uint32_t* r) {
    asm volatile("ldmatrix.sync.aligned.m8n8.x4.shared.b16 {%0,%1,%2,%3}, [%4];"
                 : "=r"(r[0]), "=r"(r[1]), "=r"(r[2]), "=r"(r[3]) : "r"(a));
}
__device__ __forceinline__ uint32_t packh(float x, float y) {
    __half2 h = __halves2half2(__float2half_rn(x), __float2half_rn(y));
    return *reinterpret_cast<uint32_t*>(&h);
}
__device__ __forceinline__ uint32_t smem_u32(const void* p) {
    uint32_t a;
    asm("{ .reg .u64 t; cvta.to.shared.u64 t, %1; cvt.u32.u64 %0, t; }" : "=r"(a) : "l"(p));
    return a;
}
__device__ __forceinline__ void cp16(uint32_t dst, const void* src) {
    asm volatile("cp.async.cg.shared.global [%0], [%1], 16;"
                 :: "r"(dst), "l"(__cvta_generic_to_global(src)) : "memory");
}
__device__ __forceinline__ void cp_commit() {
    asm volatile("cp.async.commit_group;" ::: "memory");
}
template <int N>
__device__ __forceinline__ void cp_wait() {
    asm volatile("cp.async.wait_group %0;" :: "n"(N) : "memory");
}

// ---------------------------------------------------------------------------
// merged prep kernel (unchanged from R16)
// ---------------------------------------------------------------------------
#define PREP_COPY  2560
#define PREP_PAD   512
#define PREP_SPLIT 2560
#define PREP_W     6400
#define PREP_TOTAL (PREP_COPY + PREP_PAD + PREP_SPLIT + PREP_W)

__global__ __launch_bounds__(256) void prep_kernel(
    const float4* __restrict__ pk, const float4* __restrict__ pv,
    float4* __restrict__ ko, float4* __restrict__ vo,
    const float4* __restrict__ X,
    const float* __restrict__ Wq, const float* __restrict__ Wk,
    const float* __restrict__ Wv, const float* __restrict__ Wo)
{
    __shared__ float s[32][33];
    const int blk = blockIdx.x, tid = threadIdx.x;

    if (blk < PREP_COPY) {
        int i = blk * 256 + tid;
        const int per_bh = PAST * HDIM / 4;
        int bh = i / per_bh;
        int r  = i - bh * per_bh;
        float4 kv4 = pk[i], vv4 = pv[i];
        int o  = bh * (SEQ * HDIM / 4) + r;
        ko[o] = kv4;
        vo[o] = vv4;
        int key = r / 10, d0 = (r - key * 10) * 4;
        __half2 k01 = __halves2half2(__float2half_rn(kv4.x), __float2half_rn(kv4.y));
        __half2 k23 = __halves2half2(__float2half_rn(kv4.z), __float2half_rn(kv4.w));
        __half* kh = g_Kh + ((size_t)bh * 2048 + key) * 48 + d0;
        *reinterpret_cast<__half2*>(kh)     = k01;
        *reinterpret_cast<__half2*>(kh + 2) = k23;
        __half* vt = g_Vt + ((size_t)(bh * 48 + d0)) * 2048 + key;
        vt[0]        = __float2half_rn(vv4.x);
        vt[2048]     = __float2half_rn(vv4.y);
        vt[2 * 2048] = __float2half_rn(vv4.z);
        vt[3 * 2048] = __float2half_rn(vv4.w);
    } else if (blk < PREP_COPY + PREP_PAD) {
        int i = (blk - PREP_COPY) * 256 + tid;
        uint4 z = {0u, 0u, 0u, 0u};
        *reinterpret_cast<uint4*>(g_Kh + (size_t)i * 48 + 40) = z;
    } else if (blk < PREP_COPY + PREP_PAD + PREP_SPLIT) {
        int i = (blk - PREP_COPY - PREP_PAD) * 256 + tid;
        int m = i / 320, kq = (i - m * 320) * 4;
        float4 v = X[i];
        __half hx = __float2half_rn(v.x), hy = __float2half_rn(v.y);
        __half hz = __float2half_rn(v.z), hw = __float2half_rn(v.w);
        __half* row = g_Axh + (size_t)m * KP;
        *reinterpret_cast<__half2*>(row + kq)     = __halves2half2(hx, hy);
        *reinterpret_cast<__half2*>(row + kq + 2) = __halves2half2(hz, hw);
        *reinterpret_cast<__half2*>(row + 1280 + kq) =
            __halves2half2(__float2half_rn(v.x - __half2float(hx)),
                           __float2half_rn(v.y - __half2float(hy)));
        *reinterpret_cast<__half2*>(row + 1280 + kq + 2) =
            __halves2half2(__float2half_rn(v.z - __half2float(hz)),
                           __float2half_rn(v.w - __half2float(hw)));
    } else {
        int idx = blk - (PREP_COPY + PREP_PAD + PREP_SPLIT);
        int sel = idx / 1600;
        int rem = idx - sel * 1600;
        int e0 = (rem % 40) * 32, k0 = (rem / 40) * 32;
        const float* W = (sel == 0) ? Wq : (sel == 1) ? Wk : (sel == 2) ? Wv : Wo;
        __half* dst = (sel < 3) ? (g_Bqkvh + (size_t)sel * 1280 * 1280) : g_Boh;
        int tx = tid & 31, ty = tid >> 5;
        #pragma unroll
        for (int j = 0; j < 4; j++)
            s[ty + j * 8][tx] = W[(k0 + ty + j * 8) * 1280 + e0 + tx];
        __syncthreads();
        int kk = tid & 15, ee = tid >> 4;
        int k2 = kk * 2;
        #pragma unroll
        for (int j = 0; j < 2; j++) {
            int e_loc = ee + j * 16;
            __half2 hv = __halves2half2(__float2half_rn(s[k2][e_loc]),
                                        __float2half_rn(s[k2 + 1][e_loc]));
            *reinterpret_cast<__half2*>(dst + (size_t)(e0 + e_loc) * 1280 + k0 + k2) = hv;
        }
    }
}

__device__ __forceinline__ int bcol_of(int c) {
    return (c < 40 ? c : c - 40) * KC;
}

// ---------------------------------------------------------------------------
// QKV mainloop, 128x128 tile, RUNTIME chunk count (80 for Q, 40 for K/V)
// ---------------------------------------------------------------------------
__device__ __forceinline__ void mma_tile(
    const __half* __restrict__ A, const __half* __restrict__ B,
    int m0, int n0, int nch, char* smA, char* smB, float acc[2][8][4])
{
    const int tid = threadIdx.x, lane = tid & 31, w = tid >> 5;
    const int wm = w & 3, wn = w >> 2;
    const uint32_t Ab = smem_u32(smA), Bb = smem_u32(smB);

    const uint32_t a_row_off = (uint32_t)(wm * 32 + (lane & 15)) * ROWB + (lane >> 4) * 16;
    const uint32_t b_row_off = (uint32_t)(wn * 64 + (lane & 7) + (lane >> 4) * 8) * ROWB
                             + ((lane >> 3) & 1) * 16;

    auto issue = [&](int c, int buf) {
        const uint32_t ab = Ab + buf * (128 * ROWB), bb = Bb + buf * (128 * ROWB);
        const int bc = bcol_of(c);
        #pragma unroll
        for (int i = 0; i < 2; i++) {
            int idx = tid + i * 256;
            int rr = idx >> 2, uu = idx & 3;
            cp16(ab + rr * ROWB + uu * 16,
                 A + (size_t)(m0 + rr) * KP + c * KC + uu * 8);
            cp16(bb + rr * ROWB + uu * 16,
                 B + (size_t)(n0 + rr) * 1280 + bc + uu * 8);
        }
        cp_commit();
    };

    issue(0, 0);
    for (int c = 0; c < nch; c++) {
        if (c + 1 < nch) issue(c + 1, (c + 1) & 1);
        if (c + 1 < nch) cp_wait<1>(); else cp_wait<0>();
        __syncthreads();
        const uint32_t ab = Ab + (c & 1) * (128 * ROWB);
        const uint32_t bb = Bb + (c & 1) * (128 * ROWB);
        #pragma unroll
        for (int ks = 0; ks < 2; ks++) {
            uint32_t bf[4][4];
            #pragma unroll
            for (int nb = 0; nb < 4; nb++)
                ldm4(bb + nb * (16 * ROWB) + b_row_off + ks * 32, bf[nb]);
            #pragma unroll
            for (int mi = 0; mi < 2; mi++) {
                uint32_t af[4];
                ldm4(ab + mi * (16 * ROWB) + a_row_off + ks * 32, af);
                #pragma unroll
                for (int nb = 0; nb < 4; nb++) {
                    mma16816h(acc[mi][2 * nb],     af, bf[nb]);
                    mma16816h(acc[mi][2 * nb + 1], af, bf[nb] + 2);
                }
            }
        }
        __syncthreads();
    }
}

// ---------------------------------------------------------------------------
// out-proj mainloop: 64x64 tile, KCO=64 (unchanged from R16)
// ---------------------------------------------------------------------------
__device__ __forceinline__ void mma_tile64(
    const __half* __restrict__ A, const __half* __restrict__ B,
    int m0, int n0, char* smA, char* smB, float acc[2][2][4])
{
    const int tid = threadIdx.x, lane = tid & 31, w = tid >> 5;
    const int wm = w & 1, wn = w >> 1;
    const uint32_t Ab = smem_u32(smA), Bb = smem_u32(smB);

    const uint32_t a_row_off = (uint32_t)(wm * 32 + (lane & 15)) * ROWBO + (lane >> 4) * 16;
    const uint32_t b_row_off = (uint32_t)(wn * 16 + (lane & 7) + (lane >> 4) * 8) * ROWBO
                             + ((lane >> 3) & 1) * 16;

    auto issue = [&](int c, int buf) {
        const uint32_t ab = Ab + buf * (64 * ROWBO), bb = Bb + buf * (64 * ROWBO);
        #pragma unroll
        for (int i = 0; i < 2; i++) {
            int idx = tid + i * 256;
            int rr = idx >> 3, uu = idx & 7;
            cp16(ab + rr * ROWBO + uu * 16,
                 A + (size_t)(m0 + rr) * 1280 + c * KCO + uu * 8);
            cp16(bb + rr * ROWBO + uu * 16,
                 B + (size_t)(n0 + rr) * 1280 + c * KCO + uu * 8);
        }
        cp_commit();
    };

    issue(0, 0);
    for (int c = 0; c < NCHO; c++) {
        if (c + 1 < NCHO) issue(c + 1, (c + 1) & 1);
        if (c + 1 < NCHO) cp_wait<1>(); else cp_wait<0>();
        __syncthreads();
        const uint32_t ab = Ab + (c & 1) * (64 * ROWBO);
        const uint32_t bb = Bb + (c & 1) * (64 * ROWBO);
        #pragma unroll
        for (int ks = 0; ks < 4; ks++) {
            uint32_t bf[4];
            ldm4(bb + b_row_off + ks * 32, bf);
            #pragma unroll
            for (int mi = 0; mi < 2; mi++) {
                uint32_t af[4];
                ldm4(ab + mi * (16 * ROWBO) + a_row_off + ks * 32, af);
                mma16816h(acc[mi][0], af, bf);
                mma16816h(acc[mi][1], af, bf + 2);
            }
        }
        __syncthreads();
    }
}

// ---------------------------------------------------------------------------
// GEMM kernel A: fused QKV projection. grid (16, 30).
// Q tiles: hi+lo (80 chunks); K/V tiles: hi only (40 chunks).
// ---------------------------------------------------------------------------
__global__ __launch_bounds__(256)
void gemm_qkv_mma(const float* __restrict__ bq, const float* __restrict__ bk,
                  const float* __restrict__ bv,
                  float* __restrict__ k_out, float* __restrict__ v_out)
{
    __shared__ __align__(16) char smA[2 * 128 * ROWB];
    __shared__ __align__(16) char smB[2 * 128 * ROWB];
    float acc[2][8][4];
    #pragma unroll
    for (int i = 0; i < 2; i++)
        #pragma unroll
        for (int j = 0; j < 8; j++)
            #pragma unroll
            for (int r = 0; r < 4; r++) acc[i][j][r] = 0.f;

    const int m0 = blockIdx.x * 128;
    const int which = blockIdx.y / 10;
    const int nch = (which == 0) ? NCH : NCH_HI;
    mma_tile(g_Axh, g_Bqkvh, m0, blockIdx.y * 128, nch, smA, smB, acc);

    const int lane = threadIdx.x & 31, w = threadIdx.x >> 5;
    const int wm = w & 3, wn = w >> 2;
    const int ebase = (blockIdx.y % 10) * 128 + wn * 64;

    #pragma unroll
    for (int mi = 0; mi < 2; mi++)
        #pragma unroll
        for (int ni = 0; ni < 8; ni++)
            #pragma unroll
            for (int r = 0; r < 4; r++) {
                int m = m0 + wm * 32 + mi * 16 + (lane >> 2) + ((r >> 1) & 1) * 8;
                int e = ebase + ni * 8 + (lane & 3) * 2 + (r & 1);
                int bb = m >> 10, t = m & 1023;
                int h = e / HDIM, d = e - h * HDIM;
                int bh = bb * NHEADS + h;
                float v = acc[mi][ni][r];
                if (which == 0) {
                    g_q[((size_t)bh * TGT + t) * HDIM + d] = (v + bq[e]) * SCALING;
                } else if (which == 1) {
                    float kv = v + bk[e];
                    k_out[((size_t)bh * SEQ + PAST + t) * HDIM + d] = kv;
                    g_Kh[((size_t)bh * 2048 + PAST + t) * 48 + d] = __float2half_rn(kv);
                } else {
                    float vv = v + bv[e];
                    v_out[((size_t)bh * SEQ + PAST + t) * HDIM + d] = vv;
                    g_Vt[((size_t)(bh * 48 + d)) * 2048 + PAST + t] = __float2half_rn(vv);
                }
            }
}

// ---------------------------------------------------------------------------
// GEMM kernel B: output projection. grid (32, 20), 64x64 tiles, KCO=64
// ---------------------------------------------------------------------------
__global__ __launch_bounds__(256)
void gemm_out_mma(const float* __restrict__ bo, float* __restrict__ out)
{
    __shared__ __align__(16) char smA[2 * 64 * ROWBO];
    __shared__ __align__(16) char smB[2 * 64 * ROWBO];
    float acc[2][2][4];
    #pragma unroll
    for (int i = 0; i < 2; i++)
        #pragma unroll
        for (int j = 0; j < 2; j++)
            #pragma unroll
            for (int r = 0; r < 4; r++) acc[i][j][r] = 0.f;

    const int m0 = blockIdx.x * 64;
    const int n0 = blockIdx.y * 64;
    mma_tile64(g_Aattnh, g_Boh, m0, n0, smA, smB, acc);

    const int lane = threadIdx.x & 31, w = threadIdx.x >> 5;
    const int wm = w & 1, wn = w >> 1;

    #pragma unroll
    for (int mi = 0; mi < 2; mi++)
        #pragma unroll
        for (int ni = 0; ni < 2; ni++)
            #pragma unroll
            for (int r = 0; r < 4; r++) {
                int m = m0 + wm * 32 + mi * 16 + (lane >> 2) + ((r >> 1) & 1) * 8;
                int e = n0 + wn * 16 + ni * 8 + (lane & 3) * 2 + (r & 1);
                out[(size_t)m * EMBED + e] = acc[mi][ni][r] + bo[e];
            }
}

// ---------------------------------------------------------------------------
// HMMA flash attention (R14/R16 version). grid (64, 8), 256 threads.
// ---------------------------------------------------------------------------
__global__ __launch_bounds__(256) void attn_hmma()
{
    __shared__ __align__(16) __half Kbuf[128 * 56];
    __shared__ __align__(16) __half Vbuf[48 * 136];

    const int bh = blockIdx.x;
    const int qt = blockIdx.y;
    const int b  = bh >> 5, h = bh & 31;
    const int tid = threadIdx.x, lane = tid & 31, w = tid >> 5;
    const int g = lane >> 2, tig = lane & 3;

    uint32_t qhi[3][4];
    {
        const int t0 = qt * 128 + w * 16 + g;
        const float* Q0 = g_q + ((size_t)bh * 1024 + t0) * 40;
        const float* Q1 = Q0 + 8 * 40;
        #pragma unroll
        for (int ks = 0; ks < 3; ks++)
            #pragma unroll
            for (int j = 0; j < 2; j++) {
                int k0 = ks * 16 + j * 8 + tig * 2;
                float xa0 = (k0     < 40) ? Q0[k0]     : 0.f;
                float xa1 = (k0 + 1 < 40) ? Q0[k0 + 1] : 0.f;
                float xb0 = (k0     < 40) ? Q1[k0]     : 0.f;
                float xb1 = (k0 + 1 < 40) ? Q1[k0 + 1] : 0.f;
                qhi[ks][j * 2]     = packh(xa0, xa1);
                qhi[ks][j * 2 + 1] = packh(xb0, xb1);
            }
    }

    float m_r[2] = { -1e30f, -1e30f };
    float l_r[2] = { 0.f, 0.f };
    float O[6][4];
    #pragma unroll
    for (int vt = 0; vt < 6; vt++)
        #pragma unroll
        for (int r = 0; r < 4; r++) O[vt][r] = 0.f;

    for (int ch = 0; ch < 16; ch++) {
        {
            const uint32_t* Ks = (const uint32_t*)(g_Kh + ((size_t)bh * 2048 + ch * 128) * 48);
            uint32_t* Kd = (uint32_t*)Kbuf;
            #pragma unroll
            for (int i = 0; i < 12; i++) {
                int idx = tid + i * 256;
                int r = idx / 24, cw = idx - r * 24;
                Kd[r * 28 + cw] = Ks[r * 24 + cw];
            }
            #pragma unroll
            for (int i = 0; i < 12; i++) {
                int idx = tid + i * 256;
                int d = idx >> 6, kw = idx & 63;
                ((uint32_t*)Vbuf)[d * 68 + kw] =
                    ((const uint32_t*)(g_Vt + ((size_t)(bh * 48 + d)) * 2048 + ch * 128))[kw];
            }
        }
        __syncthreads();

        float S[16][4];
        #pragma unroll
        for (int nt = 0; nt < 16; nt++)
            #pragma unroll
            for (int r = 0; r < 4; r++) S[nt][r] = 0.f;

        #pragma unroll
        for (int ks = 0; ks < 3; ks++)
            #pragma unroll
            for (int nt = 0; nt < 16; nt++) {
                uint32_t bfr[2];
                const __half* bp = Kbuf + (nt * 8 + g) * 56 + ks * 16 + tig * 2;
                bfr[0] = *(const uint32_t*)bp;
                bfr[1] = *(const uint32_t*)(bp + 8);
                mma16816h(S[nt], qhi[ks], bfr);
            }

        #pragma unroll
        for (int rh = 0; rh < 2; rh++) {
            float mx = -1e30f;
            #pragma unroll
            for (int nt = 0; nt < 16; nt++)
                mx = fmaxf(mx, fmaxf(S[nt][rh * 2], S[nt][rh * 2 + 1]));
            mx = fmaxf(mx, __shfl_xor_sync(0xffffffffu, mx, 1));
            mx = fmaxf(mx, __shfl_xor_sync(0xffffffffu, mx, 2));
            float mn   = fmaxf(m_r[rh], mx);
            float corr = __expf(m_r[rh] - mn);
            m_r[rh] = mn;
            float ls = 0.f;
            #pragma unroll
            for (int nt = 0; nt < 16; nt++) {
                float p0 = __expf(S[nt][rh * 2] - mn);
                float p1 = __expf(S[nt][rh * 2 + 1] - mn);
                S[nt][rh * 2] = p0; S[nt][rh * 2 + 1] = p1;
                ls += p0 + p1;
            }
            ls += __shfl_xor_sync(0xffffffffu, ls, 1);
            ls += __shfl_xor_sync(0xffffffffu, ls, 2);
            l_r[rh] = l_r[rh] * corr + ls;
            #pragma unroll
            for (int vt = 0; vt < 6; vt++) {
                O[vt][rh * 2] *= corr; O[vt][rh * 2 + 1] *= corr;
            }
        }

        #pragma unroll
        for (int kk = 0; kk < 8; kk++) {
            uint32_t ap[4];
            #pragma unroll
            for (int p = 0; p < 2; p++) {
                const float* Sp = S[2 * kk + p];
                ap[p * 2]     = packh(Sp[0], Sp[1]);
                ap[p * 2 + 1] = packh(Sp[2], Sp[3]);
            }
            #pragma unroll
            for (int vt = 0; vt < 6; vt++) {
                uint32_t bfr[2];
                const __half* bp = Vbuf + (vt * 8 + g) * 136 + kk * 16 + tig * 2;
                bfr[0] = *(const uint32_t*)bp;
                bfr[1] = *(const uint32_t*)(bp + 8);
                mma16816h(O[vt], ap, bfr);
            }
        }
        __syncthreads();
    }

    #pragma unroll
    for (int rh = 0; rh < 2; rh++) {
        int t = qt * 128 + w * 16 + g + rh * 8;
        int m = b * 1024 + t;
        float inv = 1.f / l_r[rh];
        __half* row = g_Aattnh + (size_t)m * 1280 + h * 40;
        #pragma unroll
        for (int vt = 0; vt < 6; vt++) {
            int d0 = vt * 8 + tig * 2;
            if (d0 < 40)     row[d0]     = __float2half_rn(O[vt][rh * 2]     * inv);
            if (d0 + 1 < 40) row[d0 + 1] = __float2half_rn(O[vt][rh * 2 + 1] * inv);
        }
    }
}

// ---------------------------------------------------------------------------
extern "C" void kernel_launch(void* const* d_in, const int* in_sizes, int n_in,
                              void* d_out, int out_size) {
    const float* X  = (const float*)d_in[0];
    const float* pk = (const float*)d_in[1];
    const float* pv = (const float*)d_in[2];
    const float* Wq = (const float*)d_in[3];
    const float* bq = (const float*)d_in[4];
    const float* Wk = (const float*)d_in[5];
    const float* bk = (const float*)d_in[6];
    const float* Wv = (const float*)d_in[7];
    const float* bv = (const float*)d_in[8];
    const float* Wo = (const float*)d_in[9];
    const float* bo = (const float*)d_in[10];

    float* out      = (float*)d_out;
    float* attn_out = out;
    float* k_out    = out + (size_t)BSZV * TGT * EMBED;
    float* v_out    = k_out + (size_t)BSZV * NHEADS * SEQ * HDIM;

    // 1) merged prep
    prep_kernel<<<PREP_TOTAL, 256>>>(
        (const float4*)pk, (const float4*)pv, (float4*)k_out, (float4*)v_out,
        (const float4*)X, Wq, Wk, Wv, Wo);
    // 2) fused QKV projection (Q: hi+lo; K/V: hi only)
    gemm_qkv_mma<<<dim3(16, 30), 256>>>(bq, bk, bv, k_out, v_out);
    // 3) attention (HMMA flash)
    attn_hmma<<<dim3(64, 8), 256>>>();
    // 4) output projection (HMMA fp16, 64x64 tiles, KCO=64)
    gemm_out_mma<<<dim3(32, 20), 256>>>(bo, attn_out);
}